// round 10
// baseline (speedup 1.0000x reference)
#include <cuda_runtime.h>
#include <cstdint>

#define CC 64
#define NSN 16
#define MAXN 65536

typedef unsigned long long u64;

// Scratch — __device__ globals per harness rules.
// g_xq holds the PRE-FOLDED attention base: b1f[c] - (x@Wq+bq)[c]*s1v[c].
__device__ float g_xq[MAXN * CC];
__device__ float g_xk[MAXN * CC];
__device__ float g_xv[MAXN * CC];

// Folded-weight struct: __device__ (divergent access) + __constant__ (uniform).
struct FW {
    float4 p2s[64];     // (p2W0*s1, p2W1*s1, p2W2*s1, s1) per channel
    float4 p2r[64];     // (p2W0, p2W1, p2W2, p2_b) raw
    float2 w1p[256];    // w1[c][2q], w1[c][2q+1]  (c*4+q)
    float  w2[64];      // w2_W[q*8+r]
    float  s2[8], c2[8], w2b[8];
    float  pA[9], pc[3];   // folded position MLP layer 1
    float  b1f[64], s1v[64];
};
__device__ FW g_fold;
__constant__ FW c_cw;

// ---- f32x2 helpers (packed fp32) ----
__device__ __forceinline__ void ffma2(u64& d, u64 a, u64 b) {
    asm("fma.rn.f32x2 %0, %1, %2, %0;" : "+l"(d) : "l"(a), "l"(b));
}
__device__ __forceinline__ u64 pk2(float x, float y) {
    u64 r; asm("mov.b64 %0, {%1, %2};" : "=l"(r) : "f"(x), "f"(y)); return r;
}
__device__ __forceinline__ float2 upk2(u64 v) {
    float2 r; asm("mov.b64 {%0, %1}, %2;" : "=f"(r.x), "=f"(r.y) : "l"(v)); return r;
}
__device__ __forceinline__ uint32_t smem_u32(const void* ptr) {
    uint32_t a;
    asm("{ .reg .u64 t; cvta.to.shared.u64 t, %1; cvt.u32.u64 %0, t; }"
        : "=r"(a) : "l"(ptr));
    return a;
}
__device__ __forceinline__ void cp_async16(uint32_t dst, const void* src) {
    asm volatile("cp.async.cg.shared.global [%0], [%1], 16;\n"
                 :: "r"(dst), "l"(src));
}
__device__ __forceinline__ void cp_commit() {
    asm volatile("cp.async.commit_group;\n" ::: "memory");
}
template <int N>
__device__ __forceinline__ void cp_wait() {
    asm volatile("cp.async.wait_group %0;\n" :: "n"(N) : "memory");
}

// ---------------------------------------------------------------------------
// Kernel A: three 64x64 GEMMs, 128 rows/block, thread tile 8x8, FFMA2.
// Block 0 additionally writes the folded-weight struct g_fold (fold kernel
// absorbed). Each block computes its own b1f/s1v inline for the m=0 epilogue.
// ---------------------------------------------------------------------------
__global__ __launch_bounds__(128) void qkv_kernel(
    const float* __restrict__ x,
    const float* __restrict__ Wq, const float* __restrict__ bq,
    const float* __restrict__ Wk, const float* __restrict__ bk,
    const float* __restrict__ Wv, const float* __restrict__ bv,
    const float* __restrict__ p1_W, const float* __restrict__ p1_b,
    const float* __restrict__ p_g,  const float* __restrict__ p_b,
    const float* __restrict__ p2_W, const float* __restrict__ p2_b,
    const float* __restrict__ w_g1, const float* __restrict__ w_b1,
    const float* __restrict__ w1_W, const float* __restrict__ w1_b,
    const float* __restrict__ w_g2, const float* __restrict__ w_b2,
    const float* __restrict__ w2_W, const float* __restrict__ w2_b)
{
    __shared__ float XsT[64][128];   // [k][r], 32 KB

    const int tid = threadIdx.x;
    const int r0  = blockIdx.x * 128;
    const float inv = rsqrtf(1.0f + 1e-5f);

    // ---- block 0: absorbed fold kernel (independent of the GEMM below) ----
    if (blockIdx.x == 0) {
        const int t = tid;
        {   // w1p: 256 entries, two per thread
            int e0 = t, e1 = t + 128;
            int c0 = e0 >> 2, q0 = e0 & 3;
            int c1 = e1 >> 2, q1 = e1 & 3;
            g_fold.w1p[e0] = make_float2(w1_W[c0 * 8 + 2 * q0], w1_W[c0 * 8 + 2 * q0 + 1]);
            g_fold.w1p[e1] = make_float2(w1_W[c1 * 8 + 2 * q1], w1_W[c1 * 8 + 2 * q1 + 1]);
        }
        if (t < 64) {
            float s1 = w_g1[t] * inv;
            float a0 = p2_W[t], a1 = p2_W[64 + t], a2 = p2_W[128 + t];
            g_fold.p2s[t] = make_float4(a0 * s1, a1 * s1, a2 * s1, s1);
            g_fold.p2r[t] = make_float4(a0, a1, a2, p2_b[t]);
            g_fold.b1f[t] = w_b1[t] + p2_b[t] * s1;
            g_fold.s1v[t] = s1;
            g_fold.w2[t]  = w2_W[t];
        } else if (t < 72) {
            int q = t - 64;
            float s2 = w_g2[q] * inv;
            g_fold.s2[q]  = s2;
            g_fold.c2[q]  = w1_b[q] * s2 + w_b2[q];
            g_fold.w2b[q] = w2_b[q];
        } else if (t < 81) {
            int q = t - 72;
            g_fold.pA[q] = p1_W[q] * (p_g[q % 3] * inv);
        } else if (t < 84) {
            int q = t - 81;
            g_fold.pc[q] = p1_b[q] * (p_g[q] * inv) + p_b[q];
        }
    }

    {
        const float* xr = x + (size_t)(r0 + tid) * 64;
        #pragma unroll
        for (int k4 = 0; k4 < 16; k4++) {
            float4 v = *(const float4*)(xr + k4 * 4);
            XsT[k4 * 4 + 0][tid] = v.x;
            XsT[k4 * 4 + 1][tid] = v.y;
            XsT[k4 * 4 + 2][tid] = v.z;
            XsT[k4 * 4 + 3][tid] = v.w;
        }
    }
    __syncthreads();

    const int tx = tid & 7;
    const int ty = tid >> 3;

    const float* Wm[3] = {Wq, Wk, Wv};
    const float* bm[3] = {bq, bk, bv};

    #pragma unroll
    for (int m = 0; m < 3; m++) {
        const float* W = Wm[m];

        u64 acc[8][4];
        #pragma unroll
        for (int j = 0; j < 8; j++)
            #pragma unroll
            for (int i = 0; i < 4; i++) acc[j][i] = 0ull;

        #pragma unroll 2
        for (int k = 0; k < 64; k++) {
            float4 a0 = *(const float4*)&XsT[k][ty * 8];
            float4 a1 = *(const float4*)&XsT[k][ty * 8 + 4];
            float4 w0 = *(const float4*)(W + k * 64 + tx * 8);
            float4 w1 = *(const float4*)(W + k * 64 + tx * 8 + 4);
            u64 wp[4] = {pk2(w0.x, w0.y), pk2(w0.z, w0.w),
                         pk2(w1.x, w1.y), pk2(w1.z, w1.w)};
            float ar[8] = {a0.x, a0.y, a0.z, a0.w, a1.x, a1.y, a1.z, a1.w};
            #pragma unroll
            for (int j = 0; j < 8; j++) {
                u64 aj = pk2(ar[j], ar[j]);
                #pragma unroll
                for (int i = 0; i < 4; i++)
                    ffma2(acc[j][i], aj, wp[i]);
            }
        }

        float bias[8];
        #pragma unroll
        for (int i = 0; i < 8; i++) bias[i] = bm[m][tx * 8 + i];

        if (m == 0) {
            // inline fold: b1f = w_b1 + p2_b*s1 ; s1 = w_g1*inv
            float bf[8], sv[8];
            #pragma unroll
            for (int i = 0; i < 8; i++) {
                float s1 = w_g1[tx * 8 + i] * inv;
                sv[i] = s1;
                bf[i] = w_b1[tx * 8 + i] + p2_b[tx * 8 + i] * s1;
            }
            #pragma unroll
            for (int j = 0; j < 8; j++) {
                size_t off = (size_t)(r0 + ty * 8 + j) * 64 + tx * 8;
                float o[8];
                #pragma unroll
                for (int i = 0; i < 4; i++) {
                    float2 v = upk2(acc[j][i]);
                    o[2*i]   = bf[2*i]   - (v.x + bias[2*i])   * sv[2*i];
                    o[2*i+1] = bf[2*i+1] - (v.y + bias[2*i+1]) * sv[2*i+1];
                }
                *(float4*)(g_xq + off)     = make_float4(o[0], o[1], o[2], o[3]);
                *(float4*)(g_xq + off + 4) = make_float4(o[4], o[5], o[6], o[7]);
            }
        } else {
            float* d = (m == 1) ? g_xk : g_xv;
            #pragma unroll
            for (int j = 0; j < 8; j++) {
                size_t off = (size_t)(r0 + ty * 8 + j) * 64 + tx * 8;
                float o[8];
                #pragma unroll
                for (int i = 0; i < 4; i++) {
                    float2 v = upk2(acc[j][i]);
                    o[2*i]   = v.x + bias[2*i];
                    o[2*i+1] = v.y + bias[2*i+1];
                }
                *(float4*)(d + off)     = make_float4(o[0], o[1], o[2], o[3]);
                *(float4*)(d + off + 4) = make_float4(o[4], o[5], o[6], o[7]);
            }
        }
    }
}

// ---------------------------------------------------------------------------
// Kernel B: attention. 16 points x 16 neighbors per block (256 threads).
// Double-buffered cp.async pipeline over 4x16-channel chunks, staged in a
// chunk-major layout [buf][q4][row][4] so every cp.async dst is 16B-aligned
// and compute-side LDS.128 is fully conflict-free.
// ---------------------------------------------------------------------------
__global__ __launch_bounds__(256, 4) void attn_kernel(
    const float* __restrict__ p,
    const int*   __restrict__ nidx,
    float* __restrict__ out)
{
    // s_k layout (phase 1): [buf(2)][q4(4)][row(256)][4 floats] = 32 KB
    __shared__ __align__(16) float s_k[2 * 4 * 256 * 4];
    __shared__ float4 s_base4[256];      // [pt][16 quads]: b1f - xq*s1 (prefolded)
    __shared__ float4 s_h4[256];         // (h0,h1,h2,-)
    __shared__ int    s_idx[256];
    __shared__ __align__(16) float s_Hx[128];  // [pt*8+cs]: sum_ns wt*h
    __shared__ __align__(16) float s_Hy[128];
    __shared__ __align__(16) float s_Hz[128];

    const int tid  = threadIdx.x;
    const int blk0 = blockIdx.x * 16;
    const uint32_t s_k_base = smem_u32(s_k);

    // base terms: straight coalesced copy (prefolded in qkv epilogue)
    s_base4[tid] = *(const float4*)(g_xq + (size_t)blk0 * 64 + tid * 4);

    const int ptl = tid >> 4, ln = tid & 15;
    const int pt  = blk0 + ptl;
    const int j   = nidx[pt * NSN + ln];
    s_idx[tid] = j;
    __syncthreads();

    // ---- issue stages for chunks 0 and 1, then do the position MLP ----
    const int q4 = tid & 3;        // which 16B quarter of the 64B chunk-row
    const int rb = tid >> 2;       // 64 rows per pass
    #pragma unroll
    for (int pre = 0; pre < 2; pre++) {
        #pragma unroll
        for (int i = 0; i < 4; i++) {
            int row = rb + 64 * i;
            int jj  = s_idx[row];
            cp_async16(s_k_base + ((pre * 4 + q4) * 256 + row) * 16,
                       g_xk + (size_t)jj * 64 + pre * 16 + q4 * 4);
        }
        cp_commit();
    }

    // position MLP (uniform weights from cmem) — overlaps the cp.async
    float h0, h1, h2;
    {
        float dp0 = p[j * 3 + 0] - p[pt * 3 + 0];
        float dp1 = p[j * 3 + 1] - p[pt * 3 + 1];
        float dp2 = p[j * 3 + 2] - p[pt * 3 + 2];
        h0 = fmaxf(fmaf(dp0, c_cw.pA[0], fmaf(dp1, c_cw.pA[3], fmaf(dp2, c_cw.pA[6], c_cw.pc[0]))), 0.f);
        h1 = fmaxf(fmaf(dp0, c_cw.pA[1], fmaf(dp1, c_cw.pA[4], fmaf(dp2, c_cw.pA[7], c_cw.pc[1]))), 0.f);
        h2 = fmaxf(fmaf(dp0, c_cw.pA[2], fmaf(dp1, c_cw.pA[5], fmaf(dp2, c_cw.pA[8], c_cw.pc[2]))), 0.f);
    }
    s_h4[tid] = make_float4(h0, h1, h2, 0.f);

    // ---- phase 1 pipeline: compute ch while ch+1 is in flight ----
    u64 a01 = 0ull, a23 = 0ull, a45 = 0ull, a67 = 0ull;

    #pragma unroll
    for (int ch = 0; ch < 4; ch++) {
        if (ch < 3) cp_wait<1>(); else cp_wait<0>();
        __syncthreads();   // everyone's chunk-ch data visible (also h, idx)

        float4 kq[4];
        #pragma unroll
        for (int c4 = 0; c4 < 4; c4++)
            kq[c4] = *(const float4*)(s_k + (((ch & 1) * 4 + c4) * 256 + tid) * 4);

        if (ch < 2) {
            __syncthreads();   // readers of buf[ch&1] done (we just copied out)
            #pragma unroll
            for (int i = 0; i < 4; i++) {
                int row = rb + 64 * i;
                int jj  = s_idx[row];
                cp_async16(s_k_base + (((ch & 1) * 4 + q4) * 256 + row) * 16,
                           g_xk + (size_t)jj * 64 + (ch + 2) * 16 + q4 * 4);
            }
            cp_commit();
        }

        #pragma unroll
        for (int c4 = 0; c4 < 4; c4++) {
            float4 gk4 = kq[c4];
            float4 bb  = s_base4[ptl * 16 + ch * 4 + c4];
            float gv[4] = {gk4.x, gk4.y, gk4.z, gk4.w};
            float bl[4] = {bb.x, bb.y, bb.z, bb.w};
            #pragma unroll
            for (int q = 0; q < 4; q++) {
                const int c = ch * 16 + c4 * 4 + q;
                float4 ps = c_cw.p2s[c];
                float a = fmaxf(fmaf(gv[q], ps.w,
                              fmaf(h0, ps.x, fmaf(h1, ps.y, fmaf(h2, ps.z, bl[q])))), 0.f);
                u64 aa = pk2(a, a);
                ffma2(a01, aa, pk2(c_cw.w1p[c * 4 + 0].x, c_cw.w1p[c * 4 + 0].y));
                ffma2(a23, aa, pk2(c_cw.w1p[c * 4 + 1].x, c_cw.w1p[c * 4 + 1].y));
                ffma2(a45, aa, pk2(c_cw.w1p[c * 4 + 2].x, c_cw.w1p[c * 4 + 2].y));
                ffma2(a67, aa, pk2(c_cw.w1p[c * 4 + 3].x, c_cw.w1p[c * 4 + 3].y));
            }
        }
    }
    __syncthreads();  // all k-tile reads done before s_k is reused

    // BN2 + ReLU + w2 -> 8 logits (uniform cmem)
    float lg[8];
    {
        float2 t01 = upk2(a01), t23 = upk2(a23), t45 = upk2(a45), t67 = upk2(a67);
        float ac[8] = {t01.x, t01.y, t23.x, t23.y, t45.x, t45.y, t67.x, t67.y};
        float u[8];
        #pragma unroll
        for (int q = 0; q < 8; q++)
            u[q] = fmaxf(fmaf(ac[q], c_cw.s2[q], c_cw.c2[q]), 0.f);
        #pragma unroll
        for (int rp = 0; rp < 4; rp++) {
            u64 acc = pk2(c_cw.w2b[2 * rp], c_cw.w2b[2 * rp + 1]);
            #pragma unroll
            for (int q = 0; q < 8; q++)
                ffma2(acc, pk2(u[q], u[q]),
                      pk2(c_cw.w2[q * 8 + 2 * rp], c_cw.w2[q * 8 + 2 * rp + 1]));
            float2 v = upk2(acc);
            lg[2 * rp] = v.x; lg[2 * rp + 1] = v.y;
        }
    }

    // softmax over the 16 neighbors (aligned 16-lane group)
    float* s_wt  = s_k;             // [pt*136 + r*17 + ns]   (for H precompute)
    float* s_wtT = s_k + 16 * 136;  // [pt*128 + ns*8 + r]    (for phase 2 LDS.128)
    float wt[8];
    #pragma unroll
    for (int r = 0; r < 8; r++) {
        float m = lg[r];
        m = fmaxf(m, __shfl_xor_sync(0xffffffffu, m, 1));
        m = fmaxf(m, __shfl_xor_sync(0xffffffffu, m, 2));
        m = fmaxf(m, __shfl_xor_sync(0xffffffffu, m, 4));
        m = fmaxf(m, __shfl_xor_sync(0xffffffffu, m, 8));
        float e = __expf(lg[r] - m);
        float s = e;
        s += __shfl_xor_sync(0xffffffffu, s, 1);
        s += __shfl_xor_sync(0xffffffffu, s, 2);
        s += __shfl_xor_sync(0xffffffffu, s, 4);
        s += __shfl_xor_sync(0xffffffffu, s, 8);
        wt[r] = __fdividef(e, s);
        s_wt[ptl * 136 + r * 17 + ln] = wt[r];
    }
    {
        float4* w4 = (float4*)(s_wtT + ptl * 128 + ln * 8);
        w4[0] = make_float4(wt[0], wt[1], wt[2], wt[3]);
        w4[1] = make_float4(wt[4], wt[5], wt[6], wt[7]);
    }
    __syncthreads();

    // ---- H precompute: H[pt][cs] = sum_ns wt[ns,cs] * h[ns]
    if (tid < 128) {
        int pl = tid >> 3, cs = tid & 7;
        float Hx = 0.f, Hy = 0.f, Hz = 0.f;
        #pragma unroll
        for (int ns = 0; ns < 16; ns++) {
            float w = s_wt[pl * 136 + cs * 17 + ns];
            float4 hh = s_h4[pl * 16 + ns];
            Hx = fmaf(w, hh.x, Hx);
            Hy = fmaf(w, hh.y, Hy);
            Hz = fmaf(w, hh.z, Hz);
        }
        s_Hx[tid] = Hx; s_Hy[tid] = Hy; s_Hz[tid] = Hz;
    }
    __syncthreads();

    // ---- phase 2: thread = (point, channel quad c=ln*4..+3), LDG.128 gather.
    // Channel c uses weight group cs = c % 8 = (ln&1)*4 + jc.
    const int half = ln & 1;
    const float* wtp = s_wtT + ptl * 128 + half * 4;
    float4 acc = make_float4(0.f, 0.f, 0.f, 0.f);
    #pragma unroll
    for (int ns = 0; ns < 16; ns++) {
        int jj   = s_idx[ptl * 16 + ns];
        float4 w = *(const float4*)(wtp + ns * 8);
        float4 v = *(const float4*)(g_xv + (size_t)jj * 64 + ln * 4);
        acc.x = fmaf(w.x, v.x, acc.x);
        acc.y = fmaf(w.y, v.y, acc.y);
        acc.z = fmaf(w.z, v.z, acc.z);
        acc.w = fmaf(w.w, v.w, acc.w);
    }
    float4 Hx4 = *(const float4*)(s_Hx + ptl * 8 + half * 4);
    float4 Hy4 = *(const float4*)(s_Hy + ptl * 8 + half * 4);
    float4 Hz4 = *(const float4*)(s_Hz + ptl * 8 + half * 4);
    float4 r;
    #pragma unroll
    for (int jc = 0; jc < 4; jc++) {
        float4 pr = g_fold.p2r[ln * 4 + jc];
        (&r.x)[jc] = (&acc.x)[jc] +
                     fmaf((&Hx4.x)[jc], pr.x,
                     fmaf((&Hy4.x)[jc], pr.y,
                     fmaf((&Hz4.x)[jc], pr.z, pr.w)));
    }
    *(float4*)(out + (size_t)pt * 64 + ln * 4) = r;
}

// ---------------------------------------------------------------------------
extern "C" void kernel_launch(void* const* d_in, const int* in_sizes, int n_in,
                              void* d_out, int out_size)
{
    const float* p    = (const float*)d_in[0];
    const float* x    = (const float*)d_in[1];
    const int*   nidx = (const int*)  d_in[2];
    const float* Wq   = (const float*)d_in[3];
    const float* bq   = (const float*)d_in[4];
    const float* Wk   = (const float*)d_in[5];
    const float* bk   = (const float*)d_in[6];
    const float* Wv   = (const float*)d_in[7];
    const float* bv   = (const float*)d_in[8];
    const float* p1W  = (const float*)d_in[9];
    const float* p1b  = (const float*)d_in[10];
    const float* pg   = (const float*)d_in[11];
    const float* pb   = (const float*)d_in[12];
    const float* p2W  = (const float*)d_in[13];
    const float* p2b  = (const float*)d_in[14];
    const float* wg1  = (const float*)d_in[15];
    const float* wb1  = (const float*)d_in[16];
    const float* w1W  = (const float*)d_in[17];
    const float* w1b  = (const float*)d_in[18];
    const float* wg2  = (const float*)d_in[19];
    const float* wb2  = (const float*)d_in[20];
    const float* w2W  = (const float*)d_in[21];
    const float* w2b  = (const float*)d_in[22];
    float* out = (float*)d_out;

    const int N = in_sizes[1] / CC;   // 65536

    qkv_kernel<<<N / 128, 128>>>(x, Wq, bq, Wk, bk, Wv, bv,
                                 p1W, p1b, pg, pb, p2W, p2b,
                                 wg1, wb1, w1W, w1b, wg2, wb2, w2W, w2b);

    void *dst = nullptr, *src = nullptr;
    cudaGetSymbolAddress(&dst, c_cw);
    cudaGetSymbolAddress(&src, g_fold);
    cudaMemcpyAsync(dst, src, sizeof(FW), cudaMemcpyDeviceToDevice, 0);

    attn_kernel<<<N / 16, 256>>>(p, nidx, out);
}

// round 11
// speedup vs baseline: 1.1963x; 1.1963x over previous
#include <cuda_runtime.h>
#include <cstdint>

#define CC 64
#define NSN 16
#define MAXN 65536

typedef unsigned long long u64;

// Scratch — __device__ globals per harness rules.
// g_xq holds the PRE-FOLDED attention base: b1f[c] - (x@Wq+bq)[c]*s1v[c].
__device__ float g_xq[MAXN * CC];
__device__ float g_xk[MAXN * CC];
__device__ float g_xv[MAXN * CC];

// Folded-weight struct: __device__ (divergent access) + __constant__ (uniform).
struct FW {
    float4 p2s[64];     // (p2W0*s1, p2W1*s1, p2W2*s1, s1) per channel
    float4 p2r[64];     // (p2W0, p2W1, p2W2, p2_b) raw
    float2 w1p[256];    // w1[c][2q], w1[c][2q+1]  (c*4+q)
    float  w2[64];      // w2_W[q*8+r]
    float  s2[8], c2[8], w2b[8];
    float  pA[9], pc[3];   // folded position MLP layer 1
    float  b1f[64], s1v[64];
};
__device__ FW g_fold;
__constant__ FW c_cw;

// ---- f32x2 helpers (packed fp32) ----
__device__ __forceinline__ void ffma2(u64& d, u64 a, u64 b) {
    asm("fma.rn.f32x2 %0, %1, %2, %0;" : "+l"(d) : "l"(a), "l"(b));
}
__device__ __forceinline__ u64 pk2(float x, float y) {
    u64 r; asm("mov.b64 %0, {%1, %2};" : "=l"(r) : "f"(x), "f"(y)); return r;
}
__device__ __forceinline__ float2 upk2(u64 v) {
    float2 r; asm("mov.b64 {%0, %1}, %2;" : "=f"(r.x), "=f"(r.y) : "l"(v)); return r;
}
__device__ __forceinline__ uint32_t smem_u32(const void* ptr) {
    uint32_t a;
    asm("{ .reg .u64 t; cvta.to.shared.u64 t, %1; cvt.u32.u64 %0, t; }"
        : "=r"(a) : "l"(ptr));
    return a;
}
__device__ __forceinline__ void cp_async16(uint32_t dst, const void* src) {
    asm volatile("cp.async.cg.shared.global [%0], [%1], 16;\n"
                 :: "r"(dst), "l"(src));
}
__device__ __forceinline__ void cp_commit() {
    asm volatile("cp.async.commit_group;\n" ::: "memory");
}
template <int N>
__device__ __forceinline__ void cp_wait() {
    asm volatile("cp.async.wait_group %0;\n" :: "n"(N) : "memory");
}

// ---------------------------------------------------------------------------
// Kernel A: three 64x64 GEMMs, 128 rows/block, thread tile 8x8, FFMA2.
// Block 0 additionally writes the folded-weight struct g_fold (fold kernel
// absorbed). Each block computes its own b1f/s1v inline for the m=0 epilogue.
// ---------------------------------------------------------------------------
__global__ __launch_bounds__(128) void qkv_kernel(
    const float* __restrict__ x,
    const float* __restrict__ Wq, const float* __restrict__ bq,
    const float* __restrict__ Wk, const float* __restrict__ bk,
    const float* __restrict__ Wv, const float* __restrict__ bv,
    const float* __restrict__ p1_W, const float* __restrict__ p1_b,
    const float* __restrict__ p_g,  const float* __restrict__ p_b,
    const float* __restrict__ p2_W, const float* __restrict__ p2_b,
    const float* __restrict__ w_g1, const float* __restrict__ w_b1,
    const float* __restrict__ w1_W, const float* __restrict__ w1_b,
    const float* __restrict__ w_g2, const float* __restrict__ w_b2,
    const float* __restrict__ w2_W, const float* __restrict__ w2_b)
{
    __shared__ float XsT[64][128];   // [k][r], 32 KB

    const int tid = threadIdx.x;
    const int r0  = blockIdx.x * 128;
    const float inv = rsqrtf(1.0f + 1e-5f);

    // ---- block 0: absorbed fold kernel (independent of the GEMM below) ----
    if (blockIdx.x == 0) {
        const int t = tid;
        {   // w1p: 256 entries, two per thread
            int e0 = t, e1 = t + 128;
            int c0 = e0 >> 2, q0 = e0 & 3;
            int c1 = e1 >> 2, q1 = e1 & 3;
            g_fold.w1p[e0] = make_float2(w1_W[c0 * 8 + 2 * q0], w1_W[c0 * 8 + 2 * q0 + 1]);
            g_fold.w1p[e1] = make_float2(w1_W[c1 * 8 + 2 * q1], w1_W[c1 * 8 + 2 * q1 + 1]);
        }
        if (t < 64) {
            float s1 = w_g1[t] * inv;
            float a0 = p2_W[t], a1 = p2_W[64 + t], a2 = p2_W[128 + t];
            g_fold.p2s[t] = make_float4(a0 * s1, a1 * s1, a2 * s1, s1);
            g_fold.p2r[t] = make_float4(a0, a1, a2, p2_b[t]);
            g_fold.b1f[t] = w_b1[t] + p2_b[t] * s1;
            g_fold.s1v[t] = s1;
            g_fold.w2[t]  = w2_W[t];
        } else if (t < 72) {
            int q = t - 64;
            float s2 = w_g2[q] * inv;
            g_fold.s2[q]  = s2;
            g_fold.c2[q]  = w1_b[q] * s2 + w_b2[q];
            g_fold.w2b[q] = w2_b[q];
        } else if (t < 81) {
            int q = t - 72;
            g_fold.pA[q] = p1_W[q] * (p_g[q % 3] * inv);
        } else if (t < 84) {
            int q = t - 81;
            g_fold.pc[q] = p1_b[q] * (p_g[q] * inv) + p_b[q];
        }
    }

    {
        const float* xr = x + (size_t)(r0 + tid) * 64;
        #pragma unroll
        for (int k4 = 0; k4 < 16; k4++) {
            float4 v = *(const float4*)(xr + k4 * 4);
            XsT[k4 * 4 + 0][tid] = v.x;
            XsT[k4 * 4 + 1][tid] = v.y;
            XsT[k4 * 4 + 2][tid] = v.z;
            XsT[k4 * 4 + 3][tid] = v.w;
        }
    }
    __syncthreads();

    const int tx = tid & 7;
    const int ty = tid >> 3;

    const float* Wm[3] = {Wq, Wk, Wv};
    const float* bm[3] = {bq, bk, bv};

    #pragma unroll
    for (int m = 0; m < 3; m++) {
        const float* W = Wm[m];

        u64 acc[8][4];
        #pragma unroll
        for (int j = 0; j < 8; j++)
            #pragma unroll
            for (int i = 0; i < 4; i++) acc[j][i] = 0ull;

        #pragma unroll 2
        for (int k = 0; k < 64; k++) {
            float4 a0 = *(const float4*)&XsT[k][ty * 8];
            float4 a1 = *(const float4*)&XsT[k][ty * 8 + 4];
            float4 w0 = *(const float4*)(W + k * 64 + tx * 8);
            float4 w1 = *(const float4*)(W + k * 64 + tx * 8 + 4);
            u64 wp[4] = {pk2(w0.x, w0.y), pk2(w0.z, w0.w),
                         pk2(w1.x, w1.y), pk2(w1.z, w1.w)};
            float ar[8] = {a0.x, a0.y, a0.z, a0.w, a1.x, a1.y, a1.z, a1.w};
            #pragma unroll
            for (int j = 0; j < 8; j++) {
                u64 aj = pk2(ar[j], ar[j]);
                #pragma unroll
                for (int i = 0; i < 4; i++)
                    ffma2(acc[j][i], aj, wp[i]);
            }
        }

        float bias[8];
        #pragma unroll
        for (int i = 0; i < 8; i++) bias[i] = bm[m][tx * 8 + i];

        if (m == 0) {
            // inline fold: b1f = w_b1 + p2_b*s1 ; s1 = w_g1*inv
            float bf[8], sv[8];
            #pragma unroll
            for (int i = 0; i < 8; i++) {
                float s1 = w_g1[tx * 8 + i] * inv;
                sv[i] = s1;
                bf[i] = w_b1[tx * 8 + i] + p2_b[tx * 8 + i] * s1;
            }
            #pragma unroll
            for (int j = 0; j < 8; j++) {
                size_t off = (size_t)(r0 + ty * 8 + j) * 64 + tx * 8;
                float o[8];
                #pragma unroll
                for (int i = 0; i < 4; i++) {
                    float2 v = upk2(acc[j][i]);
                    o[2*i]   = bf[2*i]   - (v.x + bias[2*i])   * sv[2*i];
                    o[2*i+1] = bf[2*i+1] - (v.y + bias[2*i+1]) * sv[2*i+1];
                }
                *(float4*)(g_xq + off)     = make_float4(o[0], o[1], o[2], o[3]);
                *(float4*)(g_xq + off + 4) = make_float4(o[4], o[5], o[6], o[7]);
            }
        } else {
            float* d = (m == 1) ? g_xk : g_xv;
            #pragma unroll
            for (int j = 0; j < 8; j++) {
                size_t off = (size_t)(r0 + ty * 8 + j) * 64 + tx * 8;
                float o[8];
                #pragma unroll
                for (int i = 0; i < 4; i++) {
                    float2 v = upk2(acc[j][i]);
                    o[2*i]   = v.x + bias[2*i];
                    o[2*i+1] = v.y + bias[2*i+1];
                }
                *(float4*)(d + off)     = make_float4(o[0], o[1], o[2], o[3]);
                *(float4*)(d + off + 4) = make_float4(o[4], o[5], o[6], o[7]);
            }
        }
    }
}

// ---------------------------------------------------------------------------
// Kernel B: attention (R7 structure — measured best). 16 points x 16
// neighbors per block (256 threads). Two 32-channel cp.async-staged chunks,
// stride-36 rows (144B, 16B-aligned, near-conflict-free).
// ---------------------------------------------------------------------------
__global__ __launch_bounds__(256, 4) void attn_kernel(
    const float* __restrict__ p,
    const int*   __restrict__ nidx,
    float* __restrict__ out)
{
    __shared__ __align__(16) float s_k[256 * 36]; // k tile chunks -> attn weights
    __shared__ float4 s_base4[256];      // [pt][16 quads]: b1f - xq*s1 (prefolded)
    __shared__ float4 s_h4[256];         // (h0,h1,h2,-)
    __shared__ int    s_idx[256];
    __shared__ __align__(16) float s_Hx[128];  // [pt*8+cs]: sum_ns wt*h
    __shared__ __align__(16) float s_Hy[128];
    __shared__ __align__(16) float s_Hz[128];

    const int tid  = threadIdx.x;
    const int blk0 = blockIdx.x * 16;

    // base terms: straight coalesced copy (prefolded in qkv epilogue)
    s_base4[tid] = *(const float4*)(g_xq + (size_t)blk0 * 64 + tid * 4);

    const int ptl = tid >> 4, ln = tid & 15;
    const int pt  = blk0 + ptl;
    const int j   = nidx[pt * NSN + ln];
    s_idx[tid] = j;

    // position MLP (uniform weights from cmem)
    float h0, h1, h2;
    {
        float dp0 = p[j * 3 + 0] - p[pt * 3 + 0];
        float dp1 = p[j * 3 + 1] - p[pt * 3 + 1];
        float dp2 = p[j * 3 + 2] - p[pt * 3 + 2];
        h0 = fmaxf(fmaf(dp0, c_cw.pA[0], fmaf(dp1, c_cw.pA[3], fmaf(dp2, c_cw.pA[6], c_cw.pc[0]))), 0.f);
        h1 = fmaxf(fmaf(dp0, c_cw.pA[1], fmaf(dp1, c_cw.pA[4], fmaf(dp2, c_cw.pA[7], c_cw.pc[1]))), 0.f);
        h2 = fmaxf(fmaf(dp0, c_cw.pA[2], fmaf(dp1, c_cw.pA[5], fmaf(dp2, c_cw.pA[8], c_cw.pc[2]))), 0.f);
    }
    s_h4[tid] = make_float4(h0, h1, h2, 0.f);
    __syncthreads();

    // ---- phase 1: logits MLP over 2 cp.async-staged 32-channel chunks ----
    u64 a01 = 0ull, a23 = 0ull, a45 = 0ull, a67 = 0ull;

    const uint32_t s_k_base = smem_u32(s_k);

    #pragma unroll
    for (int ch = 0; ch < 2; ch++) {
        if (ch) __syncthreads();  // chunk-0 reads done before overwrite
        {   // cooperative coalesced stage via cp.async (16B per op)
            const int q8 = tid & 7;
            const int rb = tid >> 3;
            #pragma unroll
            for (int i = 0; i < 8; i++) {
                int row = rb + 32 * i;
                int jj  = s_idx[row];
                cp_async16(s_k_base + (row * 36 + q8 * 4) * 4,
                           g_xk + (size_t)jj * 64 + ch * 32 + q8 * 4);
            }
            cp_commit();
            cp_wait<0>();
        }
        __syncthreads();

        const float4* krow4 = (const float4*)(s_k + tid * 36);
        #pragma unroll
        for (int c4 = 0; c4 < 8; c4++) {
            float4 gk4 = krow4[c4];
            float4 bb  = s_base4[ptl * 16 + ch * 8 + c4];
            float gv[4] = {gk4.x, gk4.y, gk4.z, gk4.w};
            float bl[4] = {bb.x, bb.y, bb.z, bb.w};
            #pragma unroll
            for (int q = 0; q < 4; q++) {
                const int c = ch * 32 + c4 * 4 + q;
                float4 ps = c_cw.p2s[c];
                float a = fmaxf(fmaf(gv[q], ps.w,
                              fmaf(h0, ps.x, fmaf(h1, ps.y, fmaf(h2, ps.z, bl[q])))), 0.f);
                u64 aa = pk2(a, a);
                ffma2(a01, aa, pk2(c_cw.w1p[c * 4 + 0].x, c_cw.w1p[c * 4 + 0].y));
                ffma2(a23, aa, pk2(c_cw.w1p[c * 4 + 1].x, c_cw.w1p[c * 4 + 1].y));
                ffma2(a45, aa, pk2(c_cw.w1p[c * 4 + 2].x, c_cw.w1p[c * 4 + 2].y));
                ffma2(a67, aa, pk2(c_cw.w1p[c * 4 + 3].x, c_cw.w1p[c * 4 + 3].y));
            }
        }
    }
    __syncthreads();  // all k-tile reads done before s_k is reused

    // BN2 + ReLU + w2 -> 8 logits (uniform cmem)
    float lg[8];
    {
        float2 t01 = upk2(a01), t23 = upk2(a23), t45 = upk2(a45), t67 = upk2(a67);
        float ac[8] = {t01.x, t01.y, t23.x, t23.y, t45.x, t45.y, t67.x, t67.y};
        float u[8];
        #pragma unroll
        for (int q = 0; q < 8; q++)
            u[q] = fmaxf(fmaf(ac[q], c_cw.s2[q], c_cw.c2[q]), 0.f);
        #pragma unroll
        for (int rp = 0; rp < 4; rp++) {
            u64 acc = pk2(c_cw.w2b[2 * rp], c_cw.w2b[2 * rp + 1]);
            #pragma unroll
            for (int q = 0; q < 8; q++)
                ffma2(acc, pk2(u[q], u[q]),
                      pk2(c_cw.w2[q * 8 + 2 * rp], c_cw.w2[q * 8 + 2 * rp + 1]));
            float2 v = upk2(acc);
            lg[2 * rp] = v.x; lg[2 * rp + 1] = v.y;
        }
    }

    // softmax over the 16 neighbors (aligned 16-lane group)
    float* s_wt  = s_k;             // [pt*136 + r*17 + ns]   (for H precompute)
    float* s_wtT = s_k + 16 * 136;  // [pt*128 + ns*8 + r]    (for phase 2 LDS.128)
    float wt[8];
    #pragma unroll
    for (int r = 0; r < 8; r++) {
        float m = lg[r];
        m = fmaxf(m, __shfl_xor_sync(0xffffffffu, m, 1));
        m = fmaxf(m, __shfl_xor_sync(0xffffffffu, m, 2));
        m = fmaxf(m, __shfl_xor_sync(0xffffffffu, m, 4));
        m = fmaxf(m, __shfl_xor_sync(0xffffffffu, m, 8));
        float e = __expf(lg[r] - m);
        float s = e;
        s += __shfl_xor_sync(0xffffffffu, s, 1);
        s += __shfl_xor_sync(0xffffffffu, s, 2);
        s += __shfl_xor_sync(0xffffffffu, s, 4);
        s += __shfl_xor_sync(0xffffffffu, s, 8);
        wt[r] = __fdividef(e, s);
        s_wt[ptl * 136 + r * 17 + ln] = wt[r];
    }
    {
        float4* w4 = (float4*)(s_wtT + ptl * 128 + ln * 8);
        w4[0] = make_float4(wt[0], wt[1], wt[2], wt[3]);
        w4[1] = make_float4(wt[4], wt[5], wt[6], wt[7]);
    }
    __syncthreads();

    // ---- H precompute: H[pt][cs] = sum_ns wt[ns,cs] * h[ns]
    if (tid < 128) {
        int pl = tid >> 3, cs = tid & 7;
        float Hx = 0.f, Hy = 0.f, Hz = 0.f;
        #pragma unroll
        for (int ns = 0; ns < 16; ns++) {
            float w = s_wt[pl * 136 + cs * 17 + ns];
            float4 hh = s_h4[pl * 16 + ns];
            Hx = fmaf(w, hh.x, Hx);
            Hy = fmaf(w, hh.y, Hy);
            Hz = fmaf(w, hh.z, Hz);
        }
        s_Hx[tid] = Hx; s_Hy[tid] = Hy; s_Hz[tid] = Hz;
    }
    __syncthreads();

    // ---- phase 2: thread = (point, channel quad c=ln*4..+3), LDG.128 gather.
    // Channel c uses weight group cs = c % 8 = (ln&1)*4 + jc.
    const int half = ln & 1;
    const float* wtp = s_wtT + ptl * 128 + half * 4;
    float4 acc = make_float4(0.f, 0.f, 0.f, 0.f);
    #pragma unroll
    for (int ns = 0; ns < 16; ns++) {
        int jj   = s_idx[ptl * 16 + ns];
        float4 w = *(const float4*)(wtp + ns * 8);
        float4 v = *(const float4*)(g_xv + (size_t)jj * 64 + ln * 4);
        acc.x = fmaf(w.x, v.x, acc.x);
        acc.y = fmaf(w.y, v.y, acc.y);
        acc.z = fmaf(w.z, v.z, acc.z);
        acc.w = fmaf(w.w, v.w, acc.w);
    }
    float4 Hx4 = *(const float4*)(s_Hx + ptl * 8 + half * 4);
    float4 Hy4 = *(const float4*)(s_Hy + ptl * 8 + half * 4);
    float4 Hz4 = *(const float4*)(s_Hz + ptl * 8 + half * 4);
    float4 r;
    #pragma unroll
    for (int jc = 0; jc < 4; jc++) {
        float4 pr = g_fold.p2r[ln * 4 + jc];
        (&r.x)[jc] = (&acc.x)[jc] +
                     fmaf((&Hx4.x)[jc], pr.x,
                     fmaf((&Hy4.x)[jc], pr.y,
                     fmaf((&Hz4.x)[jc], pr.z, pr.w)));
    }
    *(float4*)(out + (size_t)pt * 64 + ln * 4) = r;
}

// ---------------------------------------------------------------------------
extern "C" void kernel_launch(void* const* d_in, const int* in_sizes, int n_in,
                              void* d_out, int out_size)
{
    const float* p    = (const float*)d_in[0];
    const float* x    = (const float*)d_in[1];
    const int*   nidx = (const int*)  d_in[2];
    const float* Wq   = (const float*)d_in[3];
    const float* bq   = (const float*)d_in[4];
    const float* Wk   = (const float*)d_in[5];
    const float* bk   = (const float*)d_in[6];
    const float* Wv   = (const float*)d_in[7];
    const float* bv   = (const float*)d_in[8];
    const float* p1W  = (const float*)d_in[9];
    const float* p1b  = (const float*)d_in[10];
    const float* pg   = (const float*)d_in[11];
    const float* pb   = (const float*)d_in[12];
    const float* p2W  = (const float*)d_in[13];
    const float* p2b  = (const float*)d_in[14];
    const float* wg1  = (const float*)d_in[15];
    const float* wb1  = (const float*)d_in[16];
    const float* w1W  = (const float*)d_in[17];
    const float* w1b  = (const float*)d_in[18];
    const float* wg2  = (const float*)d_in[19];
    const float* wb2  = (const float*)d_in[20];
    const float* w2W  = (const float*)d_in[21];
    const float* w2b  = (const float*)d_in[22];
    float* out = (float*)d_out;

    const int N = in_sizes[1] / CC;   // 65536

    qkv_kernel<<<N / 128, 128>>>(x, Wq, bq, Wk, bk, Wv, bv,
                                 p1W, p1b, pg, pb, p2W, p2b,
                                 wg1, wb1, w1W, w1b, wg2, wb2, w2W, w2b);

    void *dst = nullptr, *src = nullptr;
    cudaGetSymbolAddress(&dst, c_cw);
    cudaGetSymbolAddress(&src, g_fold);
    cudaMemcpyAsync(dst, src, sizeof(FW), cudaMemcpyDeviceToDevice, 0);

    attn_kernel<<<N / 16, 256>>>(p, nidx, out);
}

// round 13
// speedup vs baseline: 1.4409x; 1.2044x over previous
#include <cuda_runtime.h>
#include <cstdint>

#define CC 64
#define NSN 16
#define MAXN 65536

typedef unsigned long long u64;

// Scratch — __device__ globals per harness rules.
// g_xq holds the PRE-FOLDED attention base: b1f[c] - (x@Wq+bq)[c]*s1v[c].
__device__ float g_xq[MAXN * CC];
__device__ float g_xk[MAXN * CC];
__device__ float g_xv[MAXN * CC];
__device__ float g_WT[3][CC * CC];   // W transposed: [n][k]

// Folded-weight struct: __device__ (divergent access) + __constant__ (uniform).
struct FW {
    float4 p2s[64];
    float4 p2r[64];
    float2 w1p[256];
    float  w2[64];
    float  s2[8], c2[8], w2b[8];
    float  pA[9], pc[3];
    float  b1f[64], s1v[64];
};
__device__ FW g_fold;
__constant__ FW c_cw;

// ---- f32x2 helpers ----
__device__ __forceinline__ void ffma2(u64& d, u64 a, u64 b) {
    asm("fma.rn.f32x2 %0, %1, %2, %0;" : "+l"(d) : "l"(a), "l"(b));
}
__device__ __forceinline__ u64 pk2(float x, float y) {
    u64 r; asm("mov.b64 %0, {%1, %2};" : "=l"(r) : "f"(x), "f"(y)); return r;
}
__device__ __forceinline__ float2 upk2(u64 v) {
    float2 r; asm("mov.b64 {%0, %1}, %2;" : "=f"(r.x), "=f"(r.y) : "l"(v)); return r;
}
__device__ __forceinline__ uint32_t smem_u32(const void* ptr) {
    uint32_t a;
    asm("{ .reg .u64 t; cvta.to.shared.u64 t, %1; cvt.u32.u64 %0, t; }"
        : "=r"(a) : "l"(ptr));
    return a;
}
__device__ __forceinline__ void cp_async16(uint32_t dst, const void* src) {
    asm volatile("cp.async.cg.shared.global [%0], [%1], 16;\n"
                 :: "r"(dst), "l"(src));
}
__device__ __forceinline__ void cp_commit() {
    asm volatile("cp.async.commit_group;\n" ::: "memory");
}
template <int N>
__device__ __forceinline__ void cp_wait() {
    asm volatile("cp.async.wait_group %0;\n" :: "n"(N) : "memory");
}
__device__ __forceinline__ uint32_t f2tf32(float f) {
    uint32_t u;
    asm("cvt.rna.tf32.f32 %0, %1;" : "=r"(u) : "f"(f));
    return u;
}
// mma m16n8k8: A row-major tf32, B col-major tf32, f32 accum (sm_80+ PTX)
__device__ __forceinline__ void mma_tf32(float* d, const uint32_t* a, const uint32_t* b) {
    asm volatile(
        "mma.sync.aligned.m16n8k8.row.col.f32.tf32.tf32.f32 "
        "{%0,%1,%2,%3}, {%4,%5,%6,%7}, {%8,%9}, {%0,%1,%2,%3};"
        : "+f"(d[0]), "+f"(d[1]), "+f"(d[2]), "+f"(d[3])
        : "r"(a[0]), "r"(a[1]), "r"(a[2]), "r"(a[3]), "r"(b[0]), "r"(b[1]));
}

// ---------------------------------------------------------------------------
// Prep kernel: blocks 0-2 transpose Wq/Wk/Wv into g_WT; block 3 = fold.
// ---------------------------------------------------------------------------
__global__ __launch_bounds__(128) void prep_kernel(
    const float* __restrict__ Wq, const float* __restrict__ Wk,
    const float* __restrict__ Wv,
    const float* __restrict__ p1_W, const float* __restrict__ p1_b,
    const float* __restrict__ p_g,  const float* __restrict__ p_b,
    const float* __restrict__ p2_W, const float* __restrict__ p2_b,
    const float* __restrict__ w_g1, const float* __restrict__ w_b1,
    const float* __restrict__ w1_W, const float* __restrict__ w1_b,
    const float* __restrict__ w_g2, const float* __restrict__ w_b2,
    const float* __restrict__ w2_W, const float* __restrict__ w2_b)
{
    const int b = blockIdx.x;
    const int tid = threadIdx.x;
    const float inv = rsqrtf(1.0f + 1e-5f);

    if (b < 3) {
        __shared__ float Ts[64 * 65];
        const float* W = (b == 0) ? Wq : (b == 1) ? Wk : Wv;
        for (int idx = tid; idx < 4096; idx += 128) {
            int k = idx >> 6, n = idx & 63;
            Ts[n * 65 + k] = W[idx];
        }
        __syncthreads();
        for (int idx = tid; idx < 4096; idx += 128) {
            int n = idx >> 6, k = idx & 63;
            g_WT[b][idx] = Ts[n * 65 + k];
        }
    } else {
        const int t = tid;
        {
            int e0 = t, e1 = t + 128;
            int c0 = e0 >> 2, q0 = e0 & 3;
            int c1 = e1 >> 2, q1 = e1 & 3;
            g_fold.w1p[e0] = make_float2(w1_W[c0 * 8 + 2 * q0], w1_W[c0 * 8 + 2 * q0 + 1]);
            g_fold.w1p[e1] = make_float2(w1_W[c1 * 8 + 2 * q1], w1_W[c1 * 8 + 2 * q1 + 1]);
        }
        if (t < 64) {
            float s1 = w_g1[t] * inv;
            float a0 = p2_W[t], a1 = p2_W[64 + t], a2 = p2_W[128 + t];
            g_fold.p2s[t] = make_float4(a0 * s1, a1 * s1, a2 * s1, s1);
            g_fold.p2r[t] = make_float4(a0, a1, a2, p2_b[t]);
            g_fold.b1f[t] = w_b1[t] + p2_b[t] * s1;
            g_fold.s1v[t] = s1;
            g_fold.w2[t]  = w2_W[t];
        } else if (t < 72) {
            int q = t - 64;
            float s2 = w_g2[q] * inv;
            g_fold.s2[q]  = s2;
            g_fold.c2[q]  = w1_b[q] * s2 + w_b2[q];
            g_fold.w2b[q] = w2_b[q];
        } else if (t < 81) {
            int q = t - 72;
            g_fold.pA[q] = p1_W[q] * (p_g[q % 3] * inv);
        } else if (t < 84) {
            int q = t - 81;
            g_fold.pc[q] = p1_b[q] * (p_g[q] * inv) + p_b[q];
        }
    }
}

// ---------------------------------------------------------------------------
// Kernel A: tf32 mma.sync qkv. 128 rows/block, 4 warps; each warp computes
// 32 rows x 64 cols via m16n8k8 tiles (2 m-tiles x 8 n-tiles x 8 k-steps).
// A (x tile) and all three B (W^T) staged tf32-converted, stride 68 -> all
// fragment LDS are bank-conflict-free. m=0 epilogue stores the folded base.
// ---------------------------------------------------------------------------
#define QS 68                     // smem row stride (floats)
#define WOFF (128 * QS)           // Ws offset (floats)
#define MOFF (320 * QS)           // misc offset (floats) = (128+192)*68
#define QKV_SMEM_BYTES ((MOFF + 320) * 4)

__global__ __launch_bounds__(128) void qkv_mma_kernel(
    const float* __restrict__ x,
    const float* __restrict__ bq, const float* __restrict__ bk,
    const float* __restrict__ bv,
    const float* __restrict__ w_g1, const float* __restrict__ w_b1,
    const float* __restrict__ p2_b)
{
    extern __shared__ __align__(16) float smf[];
    uint32_t* Xu = (uint32_t*)smf;             // [128][QS] tf32 bits
    uint32_t* Wu = (uint32_t*)(smf + WOFF);    // [3*64][QS] tf32 bits
    float*    ms = smf + MOFF;                 // bq|bk|bv|sv|bf (5*64)

    const int tid  = threadIdx.x;
    const int lane = tid & 31, warp = tid >> 5;
    const int r0   = blockIdx.x * 128;
    const float inv = rsqrtf(1.0f + 1e-5f);

    // misc vectors
    if (tid < 64) {
        int c = tid;
        float s1 = w_g1[c] * inv;
        ms[c]       = bq[c];
        ms[64 + c]  = bk[c];
        ms[128 + c] = bv[c];
        ms[192 + c] = s1;
        ms[256 + c] = w_b1[c] + p2_b[c] * s1;
    }

    // stage A: one row per thread, tf32-converted
    {
        const float* xr = x + (size_t)(r0 + tid) * 64;
        #pragma unroll
        for (int k4 = 0; k4 < 16; k4++) {
            float4 v = *(const float4*)(xr + k4 * 4);
            uint4 t;
            t.x = f2tf32(v.x); t.y = f2tf32(v.y);
            t.z = f2tf32(v.z); t.w = f2tf32(v.w);
            *(uint4*)(Xu + tid * QS + k4 * 4) = t;
        }
    }
    // stage B: rows 0..191 (= [m][n]), tf32-converted
    for (int idx = tid; idx < 192; idx += 128) {
        const float* src = g_WT[0] + idx * 64;   // g_WT is contiguous [3][4096]
        #pragma unroll
        for (int k4 = 0; k4 < 16; k4++) {
            float4 v = *(const float4*)(src + k4 * 4);
            uint4 t;
            t.x = f2tf32(v.x); t.y = f2tf32(v.y);
            t.z = f2tf32(v.z); t.w = f2tf32(v.w);
            *(uint4*)(Wu + idx * QS + k4 * 4) = t;
        }
    }
    __syncthreads();

    const int g  = lane >> 2;      // group id (0..7)
    const int tg = lane & 3;       // thread in group

    #pragma unroll
    for (int m = 0; m < 3; m++) {
        float acc[2][8][4];
        #pragma unroll
        for (int mt = 0; mt < 2; mt++)
            #pragma unroll
            for (int nt = 0; nt < 8; nt++)
                #pragma unroll
                for (int e = 0; e < 4; e++) acc[mt][nt][e] = 0.f;

        const uint32_t* Wm = Wu + m * 64 * QS;

        #pragma unroll
        for (int k8 = 0; k8 < 8; k8++) {
            const int kb = k8 * 8;
            uint32_t a[2][4];
            #pragma unroll
            for (int mt = 0; mt < 2; mt++) {
                const uint32_t* ar = Xu + (warp * 32 + mt * 16 + g) * QS + kb + tg;
                a[mt][0] = ar[0];
                a[mt][1] = ar[8 * QS];
                a[mt][2] = ar[4];
                a[mt][3] = ar[8 * QS + 4];
            }
            uint32_t b[8][2];
            #pragma unroll
            for (int nt = 0; nt < 8; nt++) {
                const uint32_t* br = Wm + (nt * 8 + g) * QS + kb + tg;
                b[nt][0] = br[0];
                b[nt][1] = br[4];
            }
            #pragma unroll
            for (int mt = 0; mt < 2; mt++)
                #pragma unroll
                for (int nt = 0; nt < 8; nt++)
                    mma_tf32(acc[mt][nt], a[mt], b[nt]);
        }

        // epilogue
        const float* bias = ms + m * 64;
        #pragma unroll
        for (int mt = 0; mt < 2; mt++) {
            const int ra = r0 + warp * 32 + mt * 16 + g;
            #pragma unroll
            for (int nt = 0; nt < 8; nt++) {
                const int c = nt * 8 + 2 * tg;
                float2 bi = *(const float2*)(bias + c);
                if (m == 0) {
                    float2 sv = *(const float2*)(ms + 192 + c);
                    float2 bf = *(const float2*)(ms + 256 + c);
                    float2 o0, o1;
                    o0.x = bf.x - (acc[mt][nt][0] + bi.x) * sv.x;
                    o0.y = bf.y - (acc[mt][nt][1] + bi.y) * sv.y;
                    o1.x = bf.x - (acc[mt][nt][2] + bi.x) * sv.x;
                    o1.y = bf.y - (acc[mt][nt][3] + bi.y) * sv.y;
                    *(float2*)(g_xq + (size_t)ra * 64 + c)       = o0;
                    *(float2*)(g_xq + (size_t)(ra + 8) * 64 + c) = o1;
                } else {
                    float* dst = (m == 1) ? g_xk : g_xv;
                    float2 o0, o1;
                    o0.x = acc[mt][nt][0] + bi.x;
                    o0.y = acc[mt][nt][1] + bi.y;
                    o1.x = acc[mt][nt][2] + bi.x;
                    o1.y = acc[mt][nt][3] + bi.y;
                    *(float2*)(dst + (size_t)ra * 64 + c)       = o0;
                    *(float2*)(dst + (size_t)(ra + 8) * 64 + c) = o1;
                }
            }
        }
    }
}

// ---------------------------------------------------------------------------
// Kernel B: attention — UNCHANGED from R11 (measured best, 85.5us).
// ---------------------------------------------------------------------------
__global__ __launch_bounds__(256, 4) void attn_kernel(
    const float* __restrict__ p,
    const int*   __restrict__ nidx,
    float* __restrict__ out)
{
    __shared__ __align__(16) float s_k[256 * 36];
    __shared__ float4 s_base4[256];
    __shared__ float4 s_h4[256];
    __shared__ int    s_idx[256];
    __shared__ __align__(16) float s_Hx[128];
    __shared__ __align__(16) float s_Hy[128];
    __shared__ __align__(16) float s_Hz[128];

    const int tid  = threadIdx.x;
    const int blk0 = blockIdx.x * 16;

    s_base4[tid] = *(const float4*)(g_xq + (size_t)blk0 * 64 + tid * 4);

    const int ptl = tid >> 4, ln = tid & 15;
    const int pt  = blk0 + ptl;
    const int j   = nidx[pt * NSN + ln];
    s_idx[tid] = j;

    float h0, h1, h2;
    {
        float dp0 = p[j * 3 + 0] - p[pt * 3 + 0];
        float dp1 = p[j * 3 + 1] - p[pt * 3 + 1];
        float dp2 = p[j * 3 + 2] - p[pt * 3 + 2];
        h0 = fmaxf(fmaf(dp0, c_cw.pA[0], fmaf(dp1, c_cw.pA[3], fmaf(dp2, c_cw.pA[6], c_cw.pc[0]))), 0.f);
        h1 = fmaxf(fmaf(dp0, c_cw.pA[1], fmaf(dp1, c_cw.pA[4], fmaf(dp2, c_cw.pA[7], c_cw.pc[1]))), 0.f);
        h2 = fmaxf(fmaf(dp0, c_cw.pA[2], fmaf(dp1, c_cw.pA[5], fmaf(dp2, c_cw.pA[8], c_cw.pc[2]))), 0.f);
    }
    s_h4[tid] = make_float4(h0, h1, h2, 0.f);
    __syncthreads();

    u64 a01 = 0ull, a23 = 0ull, a45 = 0ull, a67 = 0ull;
    const uint32_t s_k_base = smem_u32(s_k);

    #pragma unroll
    for (int ch = 0; ch < 2; ch++) {
        if (ch) __syncthreads();
        {
            const int q8 = tid & 7;
            const int rb = tid >> 3;
            #pragma unroll
            for (int i = 0; i < 8; i++) {
                int row = rb + 32 * i;
                int jj  = s_idx[row];
                cp_async16(s_k_base + (row * 36 + q8 * 4) * 4,
                           g_xk + (size_t)jj * 64 + ch * 32 + q8 * 4);
            }
            cp_commit();
            cp_wait<0>();
        }
        __syncthreads();

        const float4* krow4 = (const float4*)(s_k + tid * 36);
        #pragma unroll
        for (int c4 = 0; c4 < 8; c4++) {
            float4 gk4 = krow4[c4];
            float4 bb  = s_base4[ptl * 16 + ch * 8 + c4];
            float gv[4] = {gk4.x, gk4.y, gk4.z, gk4.w};
            float bl[4] = {bb.x, bb.y, bb.z, bb.w};
            #pragma unroll
            for (int q = 0; q < 4; q++) {
                const int c = ch * 32 + c4 * 4 + q;
                float4 ps = c_cw.p2s[c];
                float a = fmaxf(fmaf(gv[q], ps.w,
                              fmaf(h0, ps.x, fmaf(h1, ps.y, fmaf(h2, ps.z, bl[q])))), 0.f);
                u64 aa = pk2(a, a);
                ffma2(a01, aa, pk2(c_cw.w1p[c * 4 + 0].x, c_cw.w1p[c * 4 + 0].y));
                ffma2(a23, aa, pk2(c_cw.w1p[c * 4 + 1].x, c_cw.w1p[c * 4 + 1].y));
                ffma2(a45, aa, pk2(c_cw.w1p[c * 4 + 2].x, c_cw.w1p[c * 4 + 2].y));
                ffma2(a67, aa, pk2(c_cw.w1p[c * 4 + 3].x, c_cw.w1p[c * 4 + 3].y));
            }
        }
    }
    __syncthreads();

    float lg[8];
    {
        float2 t01 = upk2(a01), t23 = upk2(a23), t45 = upk2(a45), t67 = upk2(a67);
        float ac[8] = {t01.x, t01.y, t23.x, t23.y, t45.x, t45.y, t67.x, t67.y};
        float u[8];
        #pragma unroll
        for (int q = 0; q < 8; q++)
            u[q] = fmaxf(fmaf(ac[q], c_cw.s2[q], c_cw.c2[q]), 0.f);
        #pragma unroll
        for (int rp = 0; rp < 4; rp++) {
            u64 acc = pk2(c_cw.w2b[2 * rp], c_cw.w2b[2 * rp + 1]);
            #pragma unroll
            for (int q = 0; q < 8; q++)
                ffma2(acc, pk2(u[q], u[q]),
                      pk2(c_cw.w2[q * 8 + 2 * rp], c_cw.w2[q * 8 + 2 * rp + 1]));
            float2 v = upk2(acc);
            lg[2 * rp] = v.x; lg[2 * rp + 1] = v.y;
        }
    }

    float* s_wt  = s_k;
    float* s_wtT = s_k + 16 * 136;
    float wt[8];
    #pragma unroll
    for (int r = 0; r < 8; r++) {
        float m = lg[r];
        m = fmaxf(m, __shfl_xor_sync(0xffffffffu, m, 1));
        m = fmaxf(m, __shfl_xor_sync(0xffffffffu, m, 2));
        m = fmaxf(m, __shfl_xor_sync(0xffffffffu, m, 4));
        m = fmaxf(m, __shfl_xor_sync(0xffffffffu, m, 8));
        float e = __expf(lg[r] - m);
        float s = e;
        s += __shfl_xor_sync(0xffffffffu, s, 1);
        s += __shfl_xor_sync(0xffffffffu, s, 2);
        s += __shfl_xor_sync(0xffffffffu, s, 4);
        s += __shfl_xor_sync(0xffffffffu, s, 8);
        wt[r] = __fdividef(e, s);
        s_wt[ptl * 136 + r * 17 + ln] = wt[r];
    }
    {
        float4* w4 = (float4*)(s_wtT + ptl * 128 + ln * 8);
        w4[0] = make_float4(wt[0], wt[1], wt[2], wt[3]);
        w4[1] = make_float4(wt[4], wt[5], wt[6], wt[7]);
    }
    __syncthreads();

    if (tid < 128) {
        int pl = tid >> 3, cs = tid & 7;
        float Hx = 0.f, Hy = 0.f, Hz = 0.f;
        #pragma unroll
        for (int ns = 0; ns < 16; ns++) {
            float w = s_wt[pl * 136 + cs * 17 + ns];
            float4 hh = s_h4[pl * 16 + ns];
            Hx = fmaf(w, hh.x, Hx);
            Hy = fmaf(w, hh.y, Hy);
            Hz = fmaf(w, hh.z, Hz);
        }
        s_Hx[tid] = Hx; s_Hy[tid] = Hy; s_Hz[tid] = Hz;
    }
    __syncthreads();

    const int half = ln & 1;
    const float* wtp = s_wtT + ptl * 128 + half * 4;
    float4 acc = make_float4(0.f, 0.f, 0.f, 0.f);
    #pragma unroll
    for (int ns = 0; ns < 16; ns++) {
        int jj   = s_idx[ptl * 16 + ns];
        float4 w = *(const float4*)(wtp + ns * 8);
        float4 v = *(const float4*)(g_xv + (size_t)jj * 64 + ln * 4);
        acc.x = fmaf(w.x, v.x, acc.x);
        acc.y = fmaf(w.y, v.y, acc.y);
        acc.z = fmaf(w.z, v.z, acc.z);
        acc.w = fmaf(w.w, v.w, acc.w);
    }
    float4 Hx4 = *(const float4*)(s_Hx + ptl * 8 + half * 4);
    float4 Hy4 = *(const float4*)(s_Hy + ptl * 8 + half * 4);
    float4 Hz4 = *(const float4*)(s_Hz + ptl * 8 + half * 4);
    float4 r;
    #pragma unroll
    for (int jc = 0; jc < 4; jc++) {
        float4 pr = g_fold.p2r[ln * 4 + jc];
        (&r.x)[jc] = (&acc.x)[jc] +
                     fmaf((&Hx4.x)[jc], pr.x,
                     fmaf((&Hy4.x)[jc], pr.y,
                     fmaf((&Hz4.x)[jc], pr.z, pr.w)));
    }
    *(float4*)(out + (size_t)pt * 64 + ln * 4) = r;
}

// ---------------------------------------------------------------------------
extern "C" void kernel_launch(void* const* d_in, const int* in_sizes, int n_in,
                              void* d_out, int out_size)
{
    const float* p    = (const float*)d_in[0];
    const float* x    = (const float*)d_in[1];
    const int*   nidx = (const int*)  d_in[2];
    const float* Wq   = (const float*)d_in[3];
    const float* bq   = (const float*)d_in[4];
    const float* Wk   = (const float*)d_in[5];
    const float* bk   = (const float*)d_in[6];
    const float* Wv   = (const float*)d_in[7];
    const float* bv   = (const float*)d_in[8];
    const float* p1W  = (const float*)d_in[9];
    const float* p1b  = (const float*)d_in[10];
    const float* pg   = (const float*)d_in[11];
    const float* pb   = (const float*)d_in[12];
    const float* p2W  = (const float*)d_in[13];
    const float* p2b  = (const float*)d_in[14];
    const float* wg1  = (const float*)d_in[15];
    const float* wb1  = (const float*)d_in[16];
    const float* w1W  = (const float*)d_in[17];
    const float* w1b  = (const float*)d_in[18];
    const float* wg2  = (const float*)d_in[19];
    const float* wb2  = (const float*)d_in[20];
    const float* w2W  = (const float*)d_in[21];
    const float* w2b  = (const float*)d_in[22];
    float* out = (float*)d_out;

    const int N = in_sizes[1] / CC;   // 65536

    cudaFuncSetAttribute(qkv_mma_kernel,
                         cudaFuncAttributeMaxDynamicSharedMemorySize,
                         QKV_SMEM_BYTES);

    prep_kernel<<<4, 128>>>(Wq, Wk, Wv,
                            p1W, p1b, pg, pb, p2W, p2b,
                            wg1, wb1, w1W, w1b, wg2, wb2, w2W, w2b);

    qkv_mma_kernel<<<N / 128, 128, QKV_SMEM_BYTES>>>(x, bq, bk, bv, wg1, wb1, p2b);

    void *dst = nullptr, *src = nullptr;
    cudaGetSymbolAddress(&dst, c_cw);
    cudaGetSymbolAddress(&src, g_fold);
    cudaMemcpyAsync(dst, src, sizeof(FW), cudaMemcpyDeviceToDevice, 0);

    attn_kernel<<<N / 16, 256>>>(p, nidx, out);
}

// round 15
// speedup vs baseline: 1.5147x; 1.0512x over previous
#include <cuda_runtime.h>
#include <cstdint>

#define CC 64
#define NSN 16
#define MAXN 65536

typedef unsigned long long u64;

// Scratch — __device__ globals per harness rules.
// g_xq holds the PRE-FOLDED attention base: b1f[c] - (x@Wq+bq)[c]*s1v[c].
__device__ float g_xq[MAXN * CC];
__device__ float g_xk[MAXN * CC];
__device__ float g_xv[MAXN * CC];

// Folded-weight struct: __device__ (divergent access) + __constant__ (uniform).
struct FW {
    float4 p2s[64];
    float4 p2r[64];
    float2 w1p[256];
    float  w2[64];
    float  s2[8], c2[8], w2b[8];
    float  pA[9], pc[3];
    float  b1f[64], s1v[64];
};
__device__ FW g_fold;
__constant__ FW c_cw;

// ---- f32x2 helpers ----
__device__ __forceinline__ void ffma2(u64& d, u64 a, u64 b) {
    asm("fma.rn.f32x2 %0, %1, %2, %0;" : "+l"(d) : "l"(a), "l"(b));
}
__device__ __forceinline__ u64 pk2(float x, float y) {
    u64 r; asm("mov.b64 %0, {%1, %2};" : "=l"(r) : "f"(x), "f"(y)); return r;
}
__device__ __forceinline__ float2 upk2(u64 v) {
    float2 r; asm("mov.b64 {%0, %1}, %2;" : "=f"(r.x), "=f"(r.y) : "l"(v)); return r;
}
__device__ __forceinline__ uint32_t smem_u32(const void* ptr) {
    uint32_t a;
    asm("{ .reg .u64 t; cvta.to.shared.u64 t, %1; cvt.u32.u64 %0, t; }"
        : "=r"(a) : "l"(ptr));
    return a;
}
__device__ __forceinline__ void cp_async16(uint32_t dst, const void* src) {
    asm volatile("cp.async.cg.shared.global [%0], [%1], 16;\n"
                 :: "r"(dst), "l"(src));
}
__device__ __forceinline__ void cp_commit() {
    asm volatile("cp.async.commit_group;\n" ::: "memory");
}
template <int N>
__device__ __forceinline__ void cp_wait() {
    asm volatile("cp.async.wait_group %0;\n" :: "n"(N) : "memory");
}
__device__ __forceinline__ uint32_t f2tf32(float f) {
    uint32_t u;
    asm("cvt.rna.tf32.f32 %0, %1;" : "=r"(u) : "f"(f));
    return u;
}
// mma m16n8k8: A row-major tf32, B col-major tf32, f32 accum (sm_80+ PTX)
__device__ __forceinline__ void mma_tf32(float* d, const uint32_t* a, const uint32_t* b) {
    asm volatile(
        "mma.sync.aligned.m16n8k8.row.col.f32.tf32.tf32.f32 "
        "{%0,%1,%2,%3}, {%4,%5,%6,%7}, {%8,%9}, {%0,%1,%2,%3};"
        : "+f"(d[0]), "+f"(d[1]), "+f"(d[2]), "+f"(d[3])
        : "r"(a[0]), "r"(a[1]), "r"(a[2]), "r"(a[3]), "r"(b[0]), "r"(b[1]));
}

// ---------------------------------------------------------------------------
// Kernel A: tf32 mma.sync qkv. 128 rows/block, 4 warps; each warp computes
// 32 rows x 64 cols via m16n8k8 tiles (2 m-tiles x 8 n-tiles x 8 k-steps).
// B staging transposes W on the fly (no prep kernel); block 0 also writes
// the folded-weight struct g_fold. m=0 epilogue stores the folded base.
// ---------------------------------------------------------------------------
#define QS 68                     // smem row stride (floats)
#define WOFF (128 * QS)           // Ws offset (floats)
#define MOFF (320 * QS)           // misc offset (floats)
#define QKV_SMEM_BYTES ((MOFF + 320) * 4)

__global__ __launch_bounds__(128) void qkv_mma_kernel(
    const float* __restrict__ x,
    const float* __restrict__ Wq, const float* __restrict__ bq,
    const float* __restrict__ Wk, const float* __restrict__ bk,
    const float* __restrict__ Wv, const float* __restrict__ bv,
    const float* __restrict__ p1_W, const float* __restrict__ p1_b,
    const float* __restrict__ p_g,  const float* __restrict__ p_b,
    const float* __restrict__ p2_W, const float* __restrict__ p2_b,
    const float* __restrict__ w_g1, const float* __restrict__ w_b1,
    const float* __restrict__ w1_W, const float* __restrict__ w1_b,
    const float* __restrict__ w_g2, const float* __restrict__ w_b2,
    const float* __restrict__ w2_W, const float* __restrict__ w2_b)
{
    extern __shared__ __align__(16) float smf[];
    uint32_t* Xu = (uint32_t*)smf;             // [128][QS] tf32 bits
    uint32_t* Wu = (uint32_t*)(smf + WOFF);    // [3*64][QS] tf32 bits, [m*64+n][k]
    float*    ms = smf + MOFF;                 // bq|bk|bv|sv|bf (5*64)

    const int tid  = threadIdx.x;
    const int lane = tid & 31, warp = tid >> 5;
    const int r0   = blockIdx.x * 128;
    const float inv = rsqrtf(1.0f + 1e-5f);

    // ---- block 0: absorbed fold (independent of the GEMM below) ----
    if (blockIdx.x == 0) {
        const int t = tid;
        {
            int e0 = t, e1 = t + 128;
            int c0 = e0 >> 2, q0 = e0 & 3;
            int c1 = e1 >> 2, q1 = e1 & 3;
            g_fold.w1p[e0] = make_float2(w1_W[c0 * 8 + 2 * q0], w1_W[c0 * 8 + 2 * q0 + 1]);
            g_fold.w1p[e1] = make_float2(w1_W[c1 * 8 + 2 * q1], w1_W[c1 * 8 + 2 * q1 + 1]);
        }
        if (t < 64) {
            float s1 = w_g1[t] * inv;
            float a0 = p2_W[t], a1 = p2_W[64 + t], a2 = p2_W[128 + t];
            g_fold.p2s[t] = make_float4(a0 * s1, a1 * s1, a2 * s1, s1);
            g_fold.p2r[t] = make_float4(a0, a1, a2, p2_b[t]);
            g_fold.b1f[t] = w_b1[t] + p2_b[t] * s1;
            g_fold.s1v[t] = s1;
            g_fold.w2[t]  = w2_W[t];
        } else if (t < 72) {
            int q = t - 64;
            float s2 = w_g2[q] * inv;
            g_fold.s2[q]  = s2;
            g_fold.c2[q]  = w1_b[q] * s2 + w_b2[q];
            g_fold.w2b[q] = w2_b[q];
        } else if (t < 81) {
            int q = t - 72;
            g_fold.pA[q] = p1_W[q] * (p_g[q % 3] * inv);
        } else if (t < 84) {
            int q = t - 81;
            g_fold.pc[q] = p1_b[q] * (p_g[q] * inv) + p_b[q];
        }
    }

    // misc vectors
    if (tid < 64) {
        int c = tid;
        float s1 = w_g1[c] * inv;
        ms[c]       = bq[c];
        ms[64 + c]  = bk[c];
        ms[128 + c] = bv[c];
        ms[192 + c] = s1;
        ms[256 + c] = w_b1[c] + p2_b[c] * s1;
    }

    // stage A: one row per thread, tf32-converted
    {
        const float* xr = x + (size_t)(r0 + tid) * 64;
        #pragma unroll
        for (int k4 = 0; k4 < 16; k4++) {
            float4 v = *(const float4*)(xr + k4 * 4);
            uint4 t;
            t.x = f2tf32(v.x); t.y = f2tf32(v.y);
            t.z = f2tf32(v.z); t.w = f2tf32(v.w);
            *(uint4*)(Xu + tid * QS + k4 * 4) = t;
        }
    }
    // stage B: transpose W[k][n] -> Wu[(m*64+n)][k] on the fly, tf32-converted.
    // Coalesced float4 reads along n; scattered scalar STS (prologue-only cost).
    {
        #pragma unroll
        for (int it = 0; it < 24; it++) {
            int i4  = tid + it * 128;           // 0..3071
            int m   = i4 >> 10;                 // 1024 float4 per matrix
            int rem = i4 & 1023;
            int k   = rem >> 4;                 // 64 k-rows
            int n4  = rem & 15;                 // 16 float4 per k-row
            const float* Wm_ = (m == 0) ? Wq : (m == 1) ? Wk : Wv;
            float4 v = *(const float4*)(Wm_ + k * 64 + n4 * 4);
            uint32_t* dst = Wu + (m * 64 + n4 * 4) * QS + k;
            dst[0 * QS] = f2tf32(v.x);
            dst[1 * QS] = f2tf32(v.y);
            dst[2 * QS] = f2tf32(v.z);
            dst[3 * QS] = f2tf32(v.w);
        }
    }
    __syncthreads();

    const int g  = lane >> 2;      // group id (0..7)
    const int tg = lane & 3;       // thread in group

    #pragma unroll
    for (int m = 0; m < 3; m++) {
        float acc[2][8][4];
        #pragma unroll
        for (int mt = 0; mt < 2; mt++)
            #pragma unroll
            for (int nt = 0; nt < 8; nt++)
                #pragma unroll
                for (int e = 0; e < 4; e++) acc[mt][nt][e] = 0.f;

        const uint32_t* Wm = Wu + m * 64 * QS;

        #pragma unroll
        for (int k8 = 0; k8 < 8; k8++) {
            const int kb = k8 * 8;
            uint32_t a[2][4];
            #pragma unroll
            for (int mt = 0; mt < 2; mt++) {
                const uint32_t* ar = Xu + (warp * 32 + mt * 16 + g) * QS + kb + tg;
                a[mt][0] = ar[0];
                a[mt][1] = ar[8 * QS];
                a[mt][2] = ar[4];
                a[mt][3] = ar[8 * QS + 4];
            }
            uint32_t b[8][2];
            #pragma unroll
            for (int nt = 0; nt < 8; nt++) {
                const uint32_t* br = Wm + (nt * 8 + g) * QS + kb + tg;
                b[nt][0] = br[0];
                b[nt][1] = br[4];
            }
            #pragma unroll
            for (int mt = 0; mt < 2; mt++)
                #pragma unroll
                for (int nt = 0; nt < 8; nt++)
                    mma_tf32(acc[mt][nt], a[mt], b[nt]);
        }

        // epilogue
        const float* bias = ms + m * 64;
        #pragma unroll
        for (int mt = 0; mt < 2; mt++) {
            const int ra = r0 + warp * 32 + mt * 16 + g;
            #pragma unroll
            for (int nt = 0; nt < 8; nt++) {
                const int c = nt * 8 + 2 * tg;
                float2 bi = *(const float2*)(bias + c);
                if (m == 0) {
                    float2 sv = *(const float2*)(ms + 192 + c);
                    float2 bf = *(const float2*)(ms + 256 + c);
                    float2 o0, o1;
                    o0.x = bf.x - (acc[mt][nt][0] + bi.x) * sv.x;
                    o0.y = bf.y - (acc[mt][nt][1] + bi.y) * sv.y;
                    o1.x = bf.x - (acc[mt][nt][2] + bi.x) * sv.x;
                    o1.y = bf.y - (acc[mt][nt][3] + bi.y) * sv.y;
                    *(float2*)(g_xq + (size_t)ra * 64 + c)       = o0;
                    *(float2*)(g_xq + (size_t)(ra + 8) * 64 + c) = o1;
                } else {
                    float* dst = (m == 1) ? g_xk : g_xv;
                    float2 o0, o1;
                    o0.x = acc[mt][nt][0] + bi.x;
                    o0.y = acc[mt][nt][1] + bi.y;
                    o1.x = acc[mt][nt][2] + bi.x;
                    o1.y = acc[mt][nt][3] + bi.y;
                    *(float2*)(dst + (size_t)ra * 64 + c)       = o0;
                    *(float2*)(dst + (size_t)(ra + 8) * 64 + c) = o1;
                }
            }
        }
    }
}

// ---------------------------------------------------------------------------
// Kernel B: attention — UNCHANGED from R11 (measured best, 85.5us).
// ---------------------------------------------------------------------------
__global__ __launch_bounds__(256, 4) void attn_kernel(
    const float* __restrict__ p,
    const int*   __restrict__ nidx,
    float* __restrict__ out)
{
    __shared__ __align__(16) float s_k[256 * 36];
    __shared__ float4 s_base4[256];
    __shared__ float4 s_h4[256];
    __shared__ int    s_idx[256];
    __shared__ __align__(16) float s_Hx[128];
    __shared__ __align__(16) float s_Hy[128];
    __shared__ __align__(16) float s_Hz[128];

    const int tid  = threadIdx.x;
    const int blk0 = blockIdx.x * 16;

    s_base4[tid] = *(const float4*)(g_xq + (size_t)blk0 * 64 + tid * 4);

    const int ptl = tid >> 4, ln = tid & 15;
    const int pt  = blk0 + ptl;
    const int j   = nidx[pt * NSN + ln];
    s_idx[tid] = j;

    float h0, h1, h2;
    {
        float dp0 = p[j * 3 + 0] - p[pt * 3 + 0];
        float dp1 = p[j * 3 + 1] - p[pt * 3 + 1];
        float dp2 = p[j * 3 + 2] - p[pt * 3 + 2];
        h0 = fmaxf(fmaf(dp0, c_cw.pA[0], fmaf(dp1, c_cw.pA[3], fmaf(dp2, c_cw.pA[6], c_cw.pc[0]))), 0.f);
        h1 = fmaxf(fmaf(dp0, c_cw.pA[1], fmaf(dp1, c_cw.pA[4], fmaf(dp2, c_cw.pA[7], c_cw.pc[1]))), 0.f);
        h2 = fmaxf(fmaf(dp0, c_cw.pA[2], fmaf(dp1, c_cw.pA[5], fmaf(dp2, c_cw.pA[8], c_cw.pc[2]))), 0.f);
    }
    s_h4[tid] = make_float4(h0, h1, h2, 0.f);
    __syncthreads();

    u64 a01 = 0ull, a23 = 0ull, a45 = 0ull, a67 = 0ull;
    const uint32_t s_k_base = smem_u32(s_k);

    #pragma unroll
    for (int ch = 0; ch < 2; ch++) {
        if (ch) __syncthreads();
        {
            const int q8 = tid & 7;
            const int rb = tid >> 3;
            #pragma unroll
            for (int i = 0; i < 8; i++) {
                int row = rb + 32 * i;
                int jj  = s_idx[row];
                cp_async16(s_k_base + (row * 36 + q8 * 4) * 4,
                           g_xk + (size_t)jj * 64 + ch * 32 + q8 * 4);
            }
            cp_commit();
            cp_wait<0>();
        }
        __syncthreads();

        const float4* krow4 = (const float4*)(s_k + tid * 36);
        #pragma unroll
        for (int c4 = 0; c4 < 8; c4++) {
            float4 gk4 = krow4[c4];
            float4 bb  = s_base4[ptl * 16 + ch * 8 + c4];
            float gv[4] = {gk4.x, gk4.y, gk4.z, gk4.w};
            float bl[4] = {bb.x, bb.y, bb.z, bb.w};
            #pragma unroll
            for (int q = 0; q < 4; q++) {
                const int c = ch * 32 + c4 * 4 + q;
                float4 ps = c_cw.p2s[c];
                float a = fmaxf(fmaf(gv[q], ps.w,
                              fmaf(h0, ps.x, fmaf(h1, ps.y, fmaf(h2, ps.z, bl[q])))), 0.f);
                u64 aa = pk2(a, a);
                ffma2(a01, aa, pk2(c_cw.w1p[c * 4 + 0].x, c_cw.w1p[c * 4 + 0].y));
                ffma2(a23, aa, pk2(c_cw.w1p[c * 4 + 1].x, c_cw.w1p[c * 4 + 1].y));
                ffma2(a45, aa, pk2(c_cw.w1p[c * 4 + 2].x, c_cw.w1p[c * 4 + 2].y));
                ffma2(a67, aa, pk2(c_cw.w1p[c * 4 + 3].x, c_cw.w1p[c * 4 + 3].y));
            }
        }
    }
    __syncthreads();

    float lg[8];
    {
        float2 t01 = upk2(a01), t23 = upk2(a23), t45 = upk2(a45), t67 = upk2(a67);
        float ac[8] = {t01.x, t01.y, t23.x, t23.y, t45.x, t45.y, t67.x, t67.y};
        float u[8];
        #pragma unroll
        for (int q = 0; q < 8; q++)
            u[q] = fmaxf(fmaf(ac[q], c_cw.s2[q], c_cw.c2[q]), 0.f);
        #pragma unroll
        for (int rp = 0; rp < 4; rp++) {
            u64 acc = pk2(c_cw.w2b[2 * rp], c_cw.w2b[2 * rp + 1]);
            #pragma unroll
            for (int q = 0; q < 8; q++)
                ffma2(acc, pk2(u[q], u[q]),
                      pk2(c_cw.w2[q * 8 + 2 * rp], c_cw.w2[q * 8 + 2 * rp + 1]));
            float2 v = upk2(acc);
            lg[2 * rp] = v.x; lg[2 * rp + 1] = v.y;
        }
    }

    float* s_wt  = s_k;
    float* s_wtT = s_k + 16 * 136;
    float wt[8];
    #pragma unroll
    for (int r = 0; r < 8; r++) {
        float m = lg[r];
        m = fmaxf(m, __shfl_xor_sync(0xffffffffu, m, 1));
        m = fmaxf(m, __shfl_xor_sync(0xffffffffu, m, 2));
        m = fmaxf(m, __shfl_xor_sync(0xffffffffu, m, 4));
        m = fmaxf(m, __shfl_xor_sync(0xffffffffu, m, 8));
        float e = __expf(lg[r] - m);
        float s = e;
        s += __shfl_xor_sync(0xffffffffu, s, 1);
        s += __shfl_xor_sync(0xffffffffu, s, 2);
        s += __shfl_xor_sync(0xffffffffu, s, 4);
        s += __shfl_xor_sync(0xffffffffu, s, 8);
        wt[r] = __fdividef(e, s);
        s_wt[ptl * 136 + r * 17 + ln] = wt[r];
    }
    {
        float4* w4 = (float4*)(s_wtT + ptl * 128 + ln * 8);
        w4[0] = make_float4(wt[0], wt[1], wt[2], wt[3]);
        w4[1] = make_float4(wt[4], wt[5], wt[6], wt[7]);
    }
    __syncthreads();

    if (tid < 128) {
        int pl = tid >> 3, cs = tid & 7;
        float Hx = 0.f, Hy = 0.f, Hz = 0.f;
        #pragma unroll
        for (int ns = 0; ns < 16; ns++) {
            float w = s_wt[pl * 136 + cs * 17 + ns];
            float4 hh = s_h4[pl * 16 + ns];
            Hx = fmaf(w, hh.x, Hx);
            Hy = fmaf(w, hh.y, Hy);
            Hz = fmaf(w, hh.z, Hz);
        }
        s_Hx[tid] = Hx; s_Hy[tid] = Hy; s_Hz[tid] = Hz;
    }
    __syncthreads();

    const int half = ln & 1;
    const float* wtp = s_wtT + ptl * 128 + half * 4;
    float4 acc = make_float4(0.f, 0.f, 0.f, 0.f);
    #pragma unroll
    for (int ns = 0; ns < 16; ns++) {
        int jj   = s_idx[ptl * 16 + ns];
        float4 w = *(const float4*)(wtp + ns * 8);
        float4 v = *(const float4*)(g_xv + (size_t)jj * 64 + ln * 4);
        acc.x = fmaf(w.x, v.x, acc.x);
        acc.y = fmaf(w.y, v.y, acc.y);
        acc.z = fmaf(w.z, v.z, acc.z);
        acc.w = fmaf(w.w, v.w, acc.w);
    }
    float4 Hx4 = *(const float4*)(s_Hx + ptl * 8 + half * 4);
    float4 Hy4 = *(const float4*)(s_Hy + ptl * 8 + half * 4);
    float4 Hz4 = *(const float4*)(s_Hz + ptl * 8 + half * 4);
    float4 r;
    #pragma unroll
    for (int jc = 0; jc < 4; jc++) {
        float4 pr = g_fold.p2r[ln * 4 + jc];
        (&r.x)[jc] = (&acc.x)[jc] +
                     fmaf((&Hx4.x)[jc], pr.x,
                     fmaf((&Hy4.x)[jc], pr.y,
                     fmaf((&Hz4.x)[jc], pr.z, pr.w)));
    }
    *(float4*)(out + (size_t)pt * 64 + ln * 4) = r;
}

// ---------------------------------------------------------------------------
extern "C" void kernel_launch(void* const* d_in, const int* in_sizes, int n_in,
                              void* d_out, int out_size)
{
    const float* p    = (const float*)d_in[0];
    const float* x    = (const float*)d_in[1];
    const int*   nidx = (const int*)  d_in[2];
    const float* Wq   = (const float*)d_in[3];
    const float* bq   = (const float*)d_in[4];
    const float* Wk   = (const float*)d_in[5];
    const float* bk   = (const float*)d_in[6];
    const float* Wv   = (const float*)d_in[7];
    const float* bv   = (const float*)d_in[8];
    const float* p1W  = (const float*)d_in[9];
    const float* p1b  = (const float*)d_in[10];
    const float* pg   = (const float*)d_in[11];
    const float* pb   = (const float*)d_in[12];
    const float* p2W  = (const float*)d_in[13];
    const float* p2b  = (const float*)d_in[14];
    const float* wg1  = (const float*)d_in[15];
    const float* wb1  = (const float*)d_in[16];
    const float* w1W  = (const float*)d_in[17];
    const float* w1b  = (const float*)d_in[18];
    const float* wg2  = (const float*)d_in[19];
    const float* wb2  = (const float*)d_in[20];
    const float* w2W  = (const float*)d_in[21];
    const float* w2b  = (const float*)d_in[22];
    float* out = (float*)d_out;

    const int N = in_sizes[1] / CC;   // 65536

    cudaFuncSetAttribute(qkv_mma_kernel,
                         cudaFuncAttributeMaxDynamicSharedMemorySize,
                         QKV_SMEM_BYTES);

    qkv_mma_kernel<<<N / 128, 128, QKV_SMEM_BYTES>>>(
        x, Wq, bq, Wk, bk, Wv, bv,
        p1W, p1b, pg, pb, p2W, p2b,
        wg1, wb1, w1W, w1b, wg2, wb2, w2W, w2b);

    void *dst = nullptr, *src = nullptr;
    cudaGetSymbolAddress(&dst, c_cw);
    cudaGetSymbolAddress(&src, g_fold);
    cudaMemcpyAsync(dst, src, sizeof(FW), cudaMemcpyDeviceToDevice, 0);

    attn_kernel<<<N / 16, 256>>>(p, nidx, out);
}